// round 1
// baseline (speedup 1.0000x reference)
#include <cuda_runtime.h>
#include <math.h>

#define NNODES 100000
#define NEDGES 3200000
#define NF 256

// ---------------- scratch (device globals; no allocs allowed) ----------------
__device__ float g_bufA[(size_t)NNODES * NF];
__device__ float g_bufB[(size_t)NNODES * NF];
__device__ int   g_rowptr[NNODES + 1];
__device__ int   g_cursor[NNODES];
__device__ int   g_cols[NEDGES];
__device__ float g_wts[NEDGES];

// ---------------- CSR build ----------------
__global__ void hist_kernel(const int* __restrict__ erow, int E) {
    int i = blockIdx.x * blockDim.x + threadIdx.x;
    if (i < E) atomicAdd(&g_rowptr[erow[i]], 1);
}

// single block, 1024 threads: exclusive scan of g_rowptr[0..n-1], writes
// g_rowptr[n] = total, and copies offsets into g_cursor.
__global__ void scan_kernel(int n) {
    __shared__ int part[1024];
    int t = threadIdx.x;
    int CH = (n + 1023) / 1024;
    int beg = t * CH;
    int end = min(beg + CH, n);
    int s = 0;
    for (int i = beg; i < end; i++) s += g_rowptr[i];
    part[t] = s;
    __syncthreads();
    // Kogge-Stone inclusive scan
    for (int off = 1; off < 1024; off <<= 1) {
        int v = (t >= off) ? part[t - off] : 0;
        __syncthreads();
        part[t] += v;
        __syncthreads();
    }
    int base = (t == 0) ? 0 : part[t - 1];
    int run = base;
    for (int i = beg; i < end; i++) {
        int c = g_rowptr[i];
        g_rowptr[i] = run;
        g_cursor[i] = run;
        run += c;
    }
    if (t == 1023) g_rowptr[n] = part[1023];
}

__global__ void scatter_kernel(const int* __restrict__ erow,
                               const int* __restrict__ ecol,
                               const float* __restrict__ ew, int E) {
    int i = blockIdx.x * blockDim.x + threadIdx.x;
    if (i < E) {
        int r = erow[i];
        int pos = atomicAdd(&g_cursor[r], 1);
        g_cols[pos] = ecol[i];
        g_wts[pos] = ew[i];
    }
}

// ---------------- SPMM + residual: dst[i] = src[i] + sum_e w*src[col] ----------------
__global__ void spmm_res_kernel(const float* __restrict__ src,
                                float* __restrict__ dst, int n) {
    int warp = (blockIdx.x * blockDim.x + threadIdx.x) >> 5;
    if (warp >= n) return;
    int lane = threadIdx.x & 31;
    const float4* s4 = (const float4*)src;
    // residual init
    float4 a0 = s4[(size_t)warp * 64 + lane];
    float4 a1 = s4[(size_t)warp * 64 + 32 + lane];
    int beg = g_rowptr[warp], end = g_rowptr[warp + 1];
    for (int e = beg; e < end; e++) {
        int c = __ldg(&g_cols[e]);
        float w = __ldg(&g_wts[e]);
        float4 v0 = s4[(size_t)c * 64 + lane];
        float4 v1 = s4[(size_t)c * 64 + 32 + lane];
        a0.x += w * v0.x; a0.y += w * v0.y; a0.z += w * v0.z; a0.w += w * v0.w;
        a1.x += w * v1.x; a1.y += w * v1.y; a1.z += w * v1.z; a1.w += w * v1.w;
    }
    float4* d4 = (float4*)dst;
    d4[(size_t)warp * 64 + lane] = a0;
    d4[(size_t)warp * 64 + 32 + lane] = a1;
}

// ---------------- tiled SGEMM + bias (+ optional relu) ----------------
// C[M,Nc] = A[M,K] @ B[K,Nc] + bias, grid = (ceil(Nc/BN), ceil(M/BM))
template <int BM, int BN, int BK, int TM, int TN, bool RELU>
__global__ void gemm_bias_kernel(const float* __restrict__ A,
                                 const float* __restrict__ B,
                                 const float* __restrict__ bias,
                                 float* __restrict__ C, int M, int Nc, int K) {
    constexpr int THREADS = (BM / TM) * (BN / TN);
    __shared__ float As[BK][BM + 4];
    __shared__ float Bs[BK][BN];
    int tid = threadIdx.x;
    int tn = tid % (BN / TN);
    int tm = tid / (BN / TN);
    int m0 = blockIdx.y * BM, n0 = blockIdx.x * BN;
    float acc[TM][TN];
#pragma unroll
    for (int i = 0; i < TM; i++)
#pragma unroll
        for (int j = 0; j < TN; j++) acc[i][j] = 0.f;

    for (int k0 = 0; k0 < K; k0 += BK) {
#pragma unroll 2
        for (int i = tid; i < BM * BK; i += THREADS) {
            int r = i / BK, c = i % BK;
            int gm = m0 + r;
            As[c][r] = (gm < M) ? A[(size_t)gm * K + k0 + c] : 0.f;
        }
#pragma unroll 2
        for (int i = tid; i < BK * BN; i += THREADS) {
            int r = i / BN, c = i % BN;
            int gn = n0 + c;
            Bs[r][c] = (gn < Nc) ? B[(size_t)(k0 + r) * Nc + gn] : 0.f;
        }
        __syncthreads();
#pragma unroll
        for (int k = 0; k < BK; k++) {
            float av[TM], bv[TN];
#pragma unroll
            for (int i = 0; i < TM; i++) av[i] = As[k][tm * TM + i];
#pragma unroll
            for (int j = 0; j < TN; j++) bv[j] = Bs[k][tn * TN + j];
#pragma unroll
            for (int i = 0; i < TM; i++)
#pragma unroll
                for (int j = 0; j < TN; j++) acc[i][j] += av[i] * bv[j];
        }
        __syncthreads();
    }
#pragma unroll
    for (int i = 0; i < TM; i++) {
        int gm = m0 + tm * TM + i;
        if (gm >= M) continue;
#pragma unroll
        for (int j = 0; j < TN; j++) {
            int gn = n0 + tn * TN + j;
            if (gn >= Nc) continue;
            float v = acc[i][j] + bias[gn];
            if (RELU) v = fmaxf(v, 0.f);
            C[(size_t)gm * Nc + gn] = v;
        }
    }
}

// ---------------- log_softmax over 40 cols, in place, warp per row ----------------
__global__ void logsoftmax_kernel(float* __restrict__ out, int n) {
    int row = (blockIdx.x * blockDim.x + threadIdx.x) >> 5;
    if (row >= n) return;
    int lane = threadIdx.x & 31;
    float* p = out + (size_t)row * 40;
    float v0 = p[lane];
    float v1 = (lane < 8) ? p[32 + lane] : -INFINITY;
    float m = fmaxf(v0, v1);
#pragma unroll
    for (int off = 16; off; off >>= 1) m = fmaxf(m, __shfl_xor_sync(0xffffffffu, m, off));
    float s = __expf(v0 - m) + ((lane < 8) ? __expf(v1 - m) : 0.f);
#pragma unroll
    for (int off = 16; off; off >>= 1) s += __shfl_xor_sync(0xffffffffu, s, off);
    float lse = m + __logf(s);
    p[lane] = v0 - lse;
    if (lane < 8) p[32 + lane] = v1 - lse;
}

// ---------------- launch ----------------
extern "C" void kernel_launch(void* const* d_in, const int* in_sizes, int n_in,
                              void* d_out, int out_size) {
    const float* x    = (const float*)d_in[0];
    const int*   erow = (const int*)d_in[1];
    const int*   ecol = (const int*)d_in[2];
    const float* ew   = (const float*)d_in[3];
    const float* W1 = (const float*)d_in[4];
    const float* b1 = (const float*)d_in[5];
    const float* W2 = (const float*)d_in[6];
    const float* b2 = (const float*)d_in[7];
    const float* W3 = (const float*)d_in[8];
    const float* b3 = (const float*)d_in[9];
    const float* W4 = (const float*)d_in[10];
    const float* b4 = (const float*)d_in[11];
    float* out = (float*)d_out;

    int E = in_sizes[1];
    int n = in_sizes[0] / NF;

    float *bufA, *bufB;
    int* rowptr;
    cudaGetSymbolAddress((void**)&bufA, g_bufA);
    cudaGetSymbolAddress((void**)&bufB, g_bufB);
    cudaGetSymbolAddress((void**)&rowptr, g_rowptr);

    // CSR build on edge_row
    cudaMemsetAsync(rowptr, 0, (size_t)(n + 1) * sizeof(int));
    hist_kernel<<<(E + 255) / 256, 256>>>(erow, E);
    scan_kernel<<<1, 1024>>>(n);
    scatter_kernel<<<(E + 255) / 256, 256>>>(erow, ecol, ew, E);

    int spmm_blocks = (n * 32 + 255) / 256;

    // h0 = x + spmm(x)            -> bufA
    spmm_res_kernel<<<spmm_blocks, 256>>>(x, bufA, n);

    // h1 = relu(h0 @ W1 + b1)     -> bufB
    dim3 g256((NF + 127) / 128, (n + 127) / 128);
    gemm_bias_kernel<128, 128, 16, 8, 8, true><<<g256, 256>>>(bufA, W1, b1, bufB, n, NF, NF);
    // h2 = relu(h1 @ W2 + b2)     -> bufA
    gemm_bias_kernel<128, 128, 16, 8, 8, true><<<g256, 256>>>(bufB, W2, b2, bufA, n, NF, NF);
    // h3 = h2 + spmm(h2)          -> bufB
    spmm_res_kernel<<<spmm_blocks, 256>>>(bufA, bufB, n);
    // h4 = relu(h3 @ W3 + b3)     -> bufA
    gemm_bias_kernel<128, 128, 16, 8, 8, true><<<g256, 256>>>(bufB, W3, b3, bufA, n, NF, NF);
    // logits = h4 @ W4 + b4       -> d_out  (Nc=40)
    dim3 g40(1, (n + 127) / 128);
    gemm_bias_kernel<128, 64, 16, 8, 4, false><<<g40, 256>>>(bufA, W4, b4, out, n, 40, NF);
    // log_softmax in place
    logsoftmax_kernel<<<(n * 32 + 255) / 256, 256>>>(out, n);
}

// round 3
// speedup vs baseline: 1.6847x; 1.6847x over previous
#include <cuda_runtime.h>
#include <cuda_bf16.h>
#include <math.h>
#include <stdint.h>

#define NNODES 100000
#define NEDGES 3200000
#define NF 256
#define KX 768   // extended K = 3 * 256

// ---------------- scratch (device globals; no allocs allowed) ----------------
__device__ float g_bufA[(size_t)NNODES * NF];
__device__ float g_bufB[(size_t)NNODES * NF];
__device__ int   g_rowptr[NNODES + 1];
__device__ int   g_cursor[NNODES];
__device__ int   g_cols[NEDGES];
__device__ float g_wts[NEDGES];
// split+transposed weights: B'[n][k'] bf16, k' = [Bhi | Blo | Bhi]
__device__ __nv_bfloat16 g_Wp[3][NF * KX];

// ---------------- helpers ----------------
__device__ __forceinline__ uint32_t smem_u32(const void* p) {
    uint32_t a;
    asm("{ .reg .u64 t; cvta.to.shared.u64 t, %1; cvt.u32.u64 %0, t; }" : "=r"(a) : "l"(p));
    return a;
}

#define LDSM_X4(r0, r1, r2, r3, addr) \
    asm volatile("ldmatrix.sync.aligned.m8n8.x4.shared.b16 {%0,%1,%2,%3}, [%4];" \
                 : "=r"(r0), "=r"(r1), "=r"(r2), "=r"(r3) : "r"(addr))

__device__ __forceinline__ void mma_bf16(float* d, const uint32_t* a, const uint32_t* b) {
    asm volatile(
        "mma.sync.aligned.m16n8k16.row.col.f32.bf16.bf16.f32 "
        "{%0,%1,%2,%3}, {%4,%5,%6,%7}, {%8,%9}, {%0,%1,%2,%3};"
        : "+f"(d[0]), "+f"(d[1]), "+f"(d[2]), "+f"(d[3])
        : "r"(a[0]), "r"(a[1]), "r"(a[2]), "r"(a[3]), "r"(b[0]), "r"(b[1]));
}

#define CP_ASYNC16(dst, src) \
    asm volatile("cp.async.cg.shared.global [%0], [%1], 16;" :: "r"(dst), "l"(src))
#define CP_COMMIT() asm volatile("cp.async.commit_group;")
#define CP_WAIT0() asm volatile("cp.async.wait_group 0;")

// ---------------- weight prep: W[K][N] fp32 -> B'[N][KX] bf16 ----------------
__global__ void prep_w_bf16(const float* __restrict__ W, __nv_bfloat16* __restrict__ Bp) {
    int n = blockIdx.x;
    int k = threadIdx.x;
    float v = W[(size_t)k * NF + n];
    __nv_bfloat16 h = __float2bfloat16(v);
    __nv_bfloat16 l = __float2bfloat16(v - __bfloat162float(h));
    Bp[(size_t)n * KX + k] = h;
    Bp[(size_t)n * KX + 256 + k] = l;
    Bp[(size_t)n * KX + 512 + k] = h;
}

// ---------------- bf16x3 GEMM: C = relu(A[M,256] @ W + bias), N=256 ----------------
// A' = [Ahi|Ahi|Alo] built on the fly; B' precomputed. BM=128, BN=256, BK=64.
#define PITCH 72  // bf16 elems per smem row (64 + 8 pad)
#define A_STAGE (128 * PITCH * 2)
#define B_STAGE (256 * PITCH * 2)
#define GEMM_SMEM (2 * A_STAGE + 2 * B_STAGE)

__global__ void __launch_bounds__(512) gemm_bf16x3_kernel(
    const float* __restrict__ A, const __nv_bfloat16* __restrict__ Bp,
    const float* __restrict__ bias, float* __restrict__ C, int M) {
    extern __shared__ char smem[];
    uint32_t sbase = smem_u32(smem);
    uint32_t sA[2] = {sbase, sbase + A_STAGE};
    uint32_t sB[2] = {sbase + 2 * A_STAGE, sbase + 2 * A_STAGE + B_STAGE};

    int tid = threadIdx.x, lane = tid & 31, wid = tid >> 5;
    int m0 = blockIdx.x * 128;
    int wm = (wid >> 2) * 32;   // warp m-offset (4 warp rows)
    int wn = (wid & 3) * 64;    // warp n-offset (4 warp cols)

    // loader thread maps
    int arow = tid >> 2, aq = tid & 3;         // A: 128 rows x 4 quarters of 16 floats
    int gmA = m0 + arow;
    int brow = tid >> 1, bh = tid & 1;         // B: 256 rows x 2 halves of 32 bf16

    float acc[2][8][4];
#pragma unroll
    for (int i = 0; i < 2; i++)
#pragma unroll
        for (int j = 0; j < 8; j++)
#pragma unroll
            for (int q = 0; q < 4; q++) acc[i][j][q] = 0.f;

    float4 aR[4];

    // issue gmem loads for stage `it` into buffer `buf` (B via cp.async, A into regs)
    auto issue_loads = [&](int it, int buf) {
        int k0 = (it & 3) * 64;
        if (gmA < M) {
            const float4* ap = (const float4*)(A + (size_t)gmA * NF + k0 + aq * 16);
            aR[0] = ap[0]; aR[1] = ap[1]; aR[2] = ap[2]; aR[3] = ap[3];
        } else {
            aR[0] = aR[1] = aR[2] = aR[3] = make_float4(0.f, 0.f, 0.f, 0.f);
        }
        uint32_t bdst = sB[buf] + (uint32_t)(brow * PITCH + bh * 32) * 2;
        const __nv_bfloat16* bsrc = Bp + (size_t)brow * KX + it * 64 + bh * 32;
#pragma unroll
        for (int j = 0; j < 4; j++) CP_ASYNC16(bdst + j * 16, bsrc + j * 8);
        CP_COMMIT();
    };

    // convert A regs (hi for chunks 0,1; lo for chunk 2) and store to smem buf
    auto store_A = [&](int it, int buf) {
        int c = it >> 2;
        const float* av = (const float*)aR;
        uint32_t base = sA[buf] + (uint32_t)(arow * PITCH + aq * 16) * 2;
#pragma unroll
        for (int j = 0; j < 4; j++) {
            __nv_bfloat16 t[4];
#pragma unroll
            for (int e = 0; e < 4; e++) {
                float v = av[j * 4 + e];
                __nv_bfloat16 h = __float2bfloat16(v);
                t[e] = (c < 2) ? h : __float2bfloat16(v - __bfloat162float(h));
            }
            uint2 pk = *(uint2*)t;
            asm volatile("st.shared.v2.b32 [%0], {%1, %2};" :: "r"(base + j * 8),
                         "r"(pk.x), "r"(pk.y));
        }
    };

    issue_loads(0, 0);
    store_A(0, 0);
    CP_WAIT0();
    __syncthreads();

    for (int it = 0; it < 12; it++) {
        int buf = it & 1;
        if (it < 11) issue_loads(it + 1, buf ^ 1);
        // compute from stage buf
#pragma unroll
        for (int ks = 0; ks < 4; ks++) {
            uint32_t af[2][4];
#pragma unroll
            for (int mt = 0; mt < 2; mt++) {
                uint32_t addr = sA[buf] +
                    (uint32_t)((wm + mt * 16 + (lane & 15)) * PITCH + ks * 16 +
                               ((lane >> 4) << 3)) * 2;
                LDSM_X4(af[mt][0], af[mt][1], af[mt][2], af[mt][3], addr);
            }
            uint32_t bf[4][4];
#pragma unroll
            for (int p = 0; p < 4; p++) {
                uint32_t addr = sB[buf] +
                    (uint32_t)((wn + p * 16 + ((lane >> 4) << 3) + (lane & 7)) * PITCH +
                               ks * 16 + ((lane >> 3) & 1) * 8) * 2;
                LDSM_X4(bf[p][0], bf[p][1], bf[p][2], bf[p][3], addr);
            }
#pragma unroll
            for (int mt = 0; mt < 2; mt++)
#pragma unroll
                for (int nt = 0; nt < 8; nt++)
                    mma_bf16(acc[mt][nt], af[mt], &bf[nt >> 1][(nt & 1) * 2]);
        }
        if (it < 11) store_A(it + 1, buf ^ 1);
        CP_WAIT0();
        __syncthreads();
    }

    // epilogue: bias + relu, fp32 out
#pragma unroll
    for (int mt = 0; mt < 2; mt++) {
        int r0 = m0 + wm + mt * 16 + (lane >> 2);
        int r1 = r0 + 8;
#pragma unroll
        for (int nt = 0; nt < 8; nt++) {
            int n = wn + nt * 8 + (lane & 3) * 2;
            float b0 = __ldg(bias + n), b1 = __ldg(bias + n + 1);
            if (r0 < M) {
                float2 o;
                o.x = fmaxf(acc[mt][nt][0] + b0, 0.f);
                o.y = fmaxf(acc[mt][nt][1] + b1, 0.f);
                *(float2*)(C + (size_t)r0 * NF + n) = o;
            }
            if (r1 < M) {
                float2 o;
                o.x = fmaxf(acc[mt][nt][2] + b0, 0.f);
                o.y = fmaxf(acc[mt][nt][3] + b1, 0.f);
                *(float2*)(C + (size_t)r1 * NF + n) = o;
            }
        }
    }
}

// ---------------- CSR build ----------------
__global__ void hist_kernel(const int* __restrict__ erow, int E) {
    int i = blockIdx.x * blockDim.x + threadIdx.x;
    if (i < E) atomicAdd(&g_rowptr[erow[i]], 1);
}

__global__ void scan_kernel(int n) {
    __shared__ int part[1024];
    int t = threadIdx.x;
    int CH = (n + 1023) / 1024;
    int beg = t * CH;
    int end = min(beg + CH, n);
    int s = 0;
    for (int i = beg; i < end; i++) s += g_rowptr[i];
    part[t] = s;
    __syncthreads();
    for (int off = 1; off < 1024; off <<= 1) {
        int v = (t >= off) ? part[t - off] : 0;
        __syncthreads();
        part[t] += v;
        __syncthreads();
    }
    int base = (t == 0) ? 0 : part[t - 1];
    int run = base;
    for (int i = beg; i < end; i++) {
        int c = g_rowptr[i];
        g_rowptr[i] = run;
        g_cursor[i] = run;
        run += c;
    }
    if (t == 1023) g_rowptr[n] = part[1023];
}

__global__ void scatter_kernel(const int* __restrict__ erow,
                               const int* __restrict__ ecol,
                               const float* __restrict__ ew, int E) {
    int i = blockIdx.x * blockDim.x + threadIdx.x;
    if (i < E) {
        int r = erow[i];
        int pos = atomicAdd(&g_cursor[r], 1);
        g_cols[pos] = ecol[i];
        g_wts[pos] = ew[i];
    }
}

// ---------------- SPMM + residual ----------------
__global__ void spmm_res_kernel(const float* __restrict__ src,
                                float* __restrict__ dst, int n) {
    int warp = (blockIdx.x * blockDim.x + threadIdx.x) >> 5;
    if (warp >= n) return;
    int lane = threadIdx.x & 31;
    const float4* s4 = (const float4*)src;
    float4 a0 = s4[(size_t)warp * 64 + lane];
    float4 a1 = s4[(size_t)warp * 64 + 32 + lane];
    int beg = g_rowptr[warp], end = g_rowptr[warp + 1];
    for (int e = beg; e < end; e++) {
        int c = __ldg(&g_cols[e]);
        float w = __ldg(&g_wts[e]);
        float4 v0 = s4[(size_t)c * 64 + lane];
        float4 v1 = s4[(size_t)c * 64 + 32 + lane];
        a0.x += w * v0.x; a0.y += w * v0.y; a0.z += w * v0.z; a0.w += w * v0.w;
        a1.x += w * v1.x; a1.y += w * v1.y; a1.z += w * v1.z; a1.w += w * v1.w;
    }
    float4* d4 = (float4*)dst;
    d4[(size_t)warp * 64 + lane] = a0;
    d4[(size_t)warp * 64 + 32 + lane] = a1;
}

// ---------------- fp32 tiled GEMM for final N=40 layer ----------------
template <int BM, int BN, int BK, int TM, int TN, bool RELU>
__global__ void gemm_bias_kernel(const float* __restrict__ A,
                                 const float* __restrict__ B,
                                 const float* __restrict__ bias,
                                 float* __restrict__ C, int M, int Nc, int K) {
    constexpr int THREADS = (BM / TM) * (BN / TN);
    __shared__ float As[BK][BM + 4];
    __shared__ float Bs[BK][BN];
    int tid = threadIdx.x;
    int tn = tid % (BN / TN);
    int tm = tid / (BN / TN);
    int m0 = blockIdx.y * BM, n0 = blockIdx.x * BN;
    float acc[TM][TN];
#pragma unroll
    for (int i = 0; i < TM; i++)
#pragma unroll
        for (int j = 0; j < TN; j++) acc[i][j] = 0.f;

    for (int k0 = 0; k0 < K; k0 += BK) {
#pragma unroll 2
        for (int i = tid; i < BM * BK; i += THREADS) {
            int r = i / BK, c = i % BK;
            int gm = m0 + r;
            As[c][r] = (gm < M) ? A[(size_t)gm * K + k0 + c] : 0.f;
        }
#pragma unroll 2
        for (int i = tid; i < BK * BN; i += THREADS) {
            int r = i / BN, c = i % BN;
            int gn = n0 + c;
            Bs[r][c] = (gn < Nc) ? B[(size_t)(k0 + r) * Nc + gn] : 0.f;
        }
        __syncthreads();
#pragma unroll
        for (int k = 0; k < BK; k++) {
            float av[TM], bv[TN];
#pragma unroll
            for (int i = 0; i < TM; i++) av[i] = As[k][tm * TM + i];
#pragma unroll
            for (int j = 0; j < TN; j++) bv[j] = Bs[k][tn * TN + j];
#pragma unroll
            for (int i = 0; i < TM; i++)
#pragma unroll
                for (int j = 0; j < TN; j++) acc[i][j] += av[i] * bv[j];
        }
        __syncthreads();
    }
#pragma unroll
    for (int i = 0; i < TM; i++) {
        int gm = m0 + tm * TM + i;
        if (gm >= M) continue;
#pragma unroll
        for (int j = 0; j < TN; j++) {
            int gn = n0 + tn * TN + j;
            if (gn >= Nc) continue;
            float v = acc[i][j] + bias[gn];
            if (RELU) v = fmaxf(v, 0.f);
            C[(size_t)gm * Nc + gn] = v;
        }
    }
}

// ---------------- log_softmax over 40 cols, in place ----------------
__global__ void logsoftmax_kernel(float* __restrict__ out, int n) {
    int row = (blockIdx.x * blockDim.x + threadIdx.x) >> 5;
    if (row >= n) return;
    int lane = threadIdx.x & 31;
    float* p = out + (size_t)row * 40;
    float v0 = p[lane];
    float v1 = (lane < 8) ? p[32 + lane] : -INFINITY;
    float m = fmaxf(v0, v1);
#pragma unroll
    for (int off = 16; off; off >>= 1) m = fmaxf(m, __shfl_xor_sync(0xffffffffu, m, off));
    float s = __expf(v0 - m) + ((lane < 8) ? __expf(v1 - m) : 0.f);
#pragma unroll
    for (int off = 16; off; off >>= 1) s += __shfl_xor_sync(0xffffffffu, s, off);
    float lse = m + __logf(s);
    p[lane] = v0 - lse;
    if (lane < 8) p[32 + lane] = v1 - lse;
}

// ---------------- launch ----------------
extern "C" void kernel_launch(void* const* d_in, const int* in_sizes, int n_in,
                              void* d_out, int out_size) {
    const float* x    = (const float*)d_in[0];
    const int*   erow = (const int*)d_in[1];
    const int*   ecol = (const int*)d_in[2];
    const float* ew   = (const float*)d_in[3];
    const float* W1 = (const float*)d_in[4];
    const float* b1 = (const float*)d_in[5];
    const float* W2 = (const float*)d_in[6];
    const float* b2 = (const float*)d_in[7];
    const float* W3 = (const float*)d_in[8];
    const float* b3 = (const float*)d_in[9];
    const float* W4 = (const float*)d_in[10];
    const float* b4 = (const float*)d_in[11];
    float* out = (float*)d_out;

    int E = in_sizes[1];
    int n = in_sizes[0] / NF;

    float *bufA, *bufB;
    __nv_bfloat16* wp;
    int* rowptr;
    cudaGetSymbolAddress((void**)&bufA, g_bufA);
    cudaGetSymbolAddress((void**)&bufB, g_bufB);
    cudaGetSymbolAddress((void**)&rowptr, g_rowptr);
    cudaGetSymbolAddress((void**)&wp, g_Wp);

    cudaFuncSetAttribute(gemm_bf16x3_kernel, cudaFuncAttributeMaxDynamicSharedMemorySize,
                         GEMM_SMEM);

    // weight prep (transpose + bf16 split, K-extended)
    prep_w_bf16<<<256, 256>>>(W1, wp + 0 * (size_t)NF * KX);
    prep_w_bf16<<<256, 256>>>(W2, wp + 1 * (size_t)NF * KX);
    prep_w_bf16<<<256, 256>>>(W3, wp + 2 * (size_t)NF * KX);

    // CSR build
    cudaMemsetAsync(rowptr, 0, (size_t)(n + 1) * sizeof(int));
    hist_kernel<<<(E + 255) / 256, 256>>>(erow, E);
    scan_kernel<<<1, 1024>>>(n);
    scatter_kernel<<<(E + 255) / 256, 256>>>(erow, ecol, ew, E);

    int spmm_blocks = (n * 32 + 255) / 256;
    int gemm_grid = (n + 127) / 128;

    // h0 = x + spmm(x)                     -> bufA
    spmm_res_kernel<<<spmm_blocks, 256>>>(x, bufA, n);
    // h1 = relu(h0 @ W1 + b1)              -> bufB
    gemm_bf16x3_kernel<<<gemm_grid, 512, GEMM_SMEM>>>(bufA, wp + 0 * (size_t)NF * KX, b1,
                                                      bufB, n);
    // h2 = relu(h1 @ W2 + b2)              -> bufA
    gemm_bf16x3_kernel<<<gemm_grid, 512, GEMM_SMEM>>>(bufB, wp + 1 * (size_t)NF * KX, b2,
                                                      bufA, n);
    // h3 = h2 + spmm(h2)                   -> bufB
    spmm_res_kernel<<<spmm_blocks, 256>>>(bufA, bufB, n);
    // h4 = relu(h3 @ W3 + b3)              -> bufA
    gemm_bf16x3_kernel<<<gemm_grid, 512, GEMM_SMEM>>>(bufB, wp + 2 * (size_t)NF * KX, b3,
                                                      bufA, n);
    // logits = h4 @ W4 + b4                -> d_out (Nc=40)
    dim3 g40(1, (n + 127) / 128);
    gemm_bias_kernel<128, 64, 16, 8, 4, false><<<g40, 256>>>(bufA, W4, b4, out, n, 40, NF);
    // log_softmax in place
    logsoftmax_kernel<<<(n * 32 + 255) / 256, 256>>>(out, n);
}

// round 4
// speedup vs baseline: 1.8542x; 1.1006x over previous
#include <cuda_runtime.h>
#include <cuda_bf16.h>
#include <math.h>
#include <stdint.h>

#define NNODES 100000
#define NEDGES 3200000
#define NF 256
#define KX 768   // extended K = 3 * 256 (kc-major: per 64-chunk [Bhi|Blo|Bhi])

// ---------------- scratch (device globals; no allocs allowed) ----------------
__device__ float g_bufA[(size_t)NNODES * NF];
__device__ float g_bufB[(size_t)NNODES * NF];
__device__ int   g_rowptr[NNODES + 1];
__device__ int   g_cursor[NNODES];
__device__ int   g_cols[NEDGES];
__device__ float g_wts[NEDGES];
__device__ __nv_bfloat16 g_Wp[3][NF * KX];

// ---------------- helpers ----------------
__device__ __forceinline__ uint32_t smem_u32(const void* p) {
    uint32_t a;
    asm("{ .reg .u64 t; cvta.to.shared.u64 t, %1; cvt.u32.u64 %0, t; }" : "=r"(a) : "l"(p));
    return a;
}

#define LDSM_X4(r0, r1, r2, r3, addr) \
    asm volatile("ldmatrix.sync.aligned.m8n8.x4.shared.b16 {%0,%1,%2,%3}, [%4];" \
                 : "=r"(r0), "=r"(r1), "=r"(r2), "=r"(r3) : "r"(addr))

__device__ __forceinline__ void mma_bf16(float* d, const uint32_t* a, const uint32_t* b) {
    asm volatile(
        "mma.sync.aligned.m16n8k16.row.col.f32.bf16.bf16.f32 "
        "{%0,%1,%2,%3}, {%4,%5,%6,%7}, {%8,%9}, {%0,%1,%2,%3};"
        : "+f"(d[0]), "+f"(d[1]), "+f"(d[2]), "+f"(d[3])
        : "r"(a[0]), "r"(a[1]), "r"(a[2]), "r"(a[3]), "r"(b[0]), "r"(b[1]));
}

#define CP_ASYNC16(dst, src) \
    asm volatile("cp.async.cg.shared.global [%0], [%1], 16;" :: "r"(dst), "l"(src))
#define CP_COMMIT() asm volatile("cp.async.commit_group;")
#define CP_WAIT0() asm volatile("cp.async.wait_group 0;")

// ---------------- weight prep: W[K][N] fp32 -> B'[N][KX] bf16, kc-major ----------------
__global__ void prep_w_bf16(const float* __restrict__ W, __nv_bfloat16* __restrict__ Bp) {
    int n = blockIdx.x;
    int k = threadIdx.x;
    float v = W[(size_t)k * NF + n];
    __nv_bfloat16 h = __float2bfloat16(v);
    __nv_bfloat16 l = __float2bfloat16(v - __bfloat162float(h));
    int kc = k >> 6, kr = k & 63;
    __nv_bfloat16* dst = Bp + (size_t)n * KX + kc * 192 + kr;
    dst[0] = h;      // p0: Ahi*Bhi
    dst[64] = l;     // p1: Ahi*Blo
    dst[128] = h;    // p2: Alo*Bhi
}

// ---------------- bf16x3 GEMM: C = relu(A[M,256] @ W + bias), N=256 ----------------
#define PITCH 72
#define A_STAGE (128 * PITCH * 2)
#define B_STAGE (256 * PITCH * 2)
#define GEMM_SMEM (2 * A_STAGE + 2 * B_STAGE)

__global__ void __launch_bounds__(512) gemm_bf16x3_kernel(
    const float* __restrict__ A, const __nv_bfloat16* __restrict__ Bp,
    const float* __restrict__ bias, float* __restrict__ C, int M) {
    extern __shared__ char smem[];
    uint32_t sbase = smem_u32(smem);
    uint32_t sAhi = sbase, sAlo = sbase + A_STAGE;
    uint32_t sB[2] = {sbase + 2 * A_STAGE, sbase + 2 * A_STAGE + B_STAGE};

    int tid = threadIdx.x, lane = tid & 31, wid = tid >> 5;
    int m0 = blockIdx.x * 128;
    int wm = (wid >> 2) * 32;
    int wn = (wid & 3) * 64;

    int arow = tid >> 2, aq = tid & 3;
    int gmA = m0 + arow;
    int brow = tid >> 1, bh = tid & 1;

    float acc[2][8][4];
#pragma unroll
    for (int i = 0; i < 2; i++)
#pragma unroll
        for (int j = 0; j < 8; j++)
#pragma unroll
            for (int q = 0; q < 4; q++) acc[i][j][q] = 0.f;

    float4 aR[4];

    auto load_A = [&](int kc) {
        int k0 = kc * 64;
        if (gmA < M) {
            const float4* ap = (const float4*)(A + (size_t)gmA * NF + k0 + aq * 16);
            aR[0] = ap[0]; aR[1] = ap[1]; aR[2] = ap[2]; aR[3] = ap[3];
        } else {
            aR[0] = aR[1] = aR[2] = aR[3] = make_float4(0.f, 0.f, 0.f, 0.f);
        }
    };

    auto store_A_both = [&]() {
        const float* av = (const float*)aR;
        uint32_t off = (uint32_t)(arow * PITCH + aq * 16) * 2;
#pragma unroll
        for (int j = 0; j < 4; j++) {
            __nv_bfloat16 h[4], l[4];
#pragma unroll
            for (int e = 0; e < 4; e++) {
                float v = av[j * 4 + e];
                h[e] = __float2bfloat16(v);
                l[e] = __float2bfloat16(v - __bfloat162float(h[e]));
            }
            uint2 ph = *(uint2*)h;
            uint2 pl = *(uint2*)l;
            asm volatile("st.shared.v2.b32 [%0], {%1, %2};"
                         :: "r"(sAhi + off + j * 8), "r"(ph.x), "r"(ph.y));
            asm volatile("st.shared.v2.b32 [%0], {%1, %2};"
                         :: "r"(sAlo + off + j * 8), "r"(pl.x), "r"(pl.y));
        }
    };

    auto issue_B = [&](int it, int buf) {
        uint32_t bdst = sB[buf] + (uint32_t)(brow * PITCH + bh * 32) * 2;
        const __nv_bfloat16* bsrc = Bp + (size_t)brow * KX + it * 64 + bh * 32;
#pragma unroll
        for (int j = 0; j < 4; j++) CP_ASYNC16(bdst + j * 16, bsrc + j * 8);
        CP_COMMIT();
    };

    auto compute = [&](uint32_t sA, uint32_t sBb) {
#pragma unroll
        for (int ks = 0; ks < 4; ks++) {
            uint32_t af[2][4];
#pragma unroll
            for (int mt = 0; mt < 2; mt++) {
                uint32_t addr = sA +
                    (uint32_t)((wm + mt * 16 + (lane & 15)) * PITCH + ks * 16 +
                               ((lane >> 4) << 3)) * 2;
                LDSM_X4(af[mt][0], af[mt][1], af[mt][2], af[mt][3], addr);
            }
            uint32_t bf[4][4];
#pragma unroll
            for (int p = 0; p < 4; p++) {
                uint32_t addr = sBb +
                    (uint32_t)((wn + p * 16 + ((lane >> 4) << 3) + (lane & 7)) * PITCH +
                               ks * 16 + ((lane >> 3) & 1) * 8) * 2;
                LDSM_X4(bf[p][0], bf[p][1], bf[p][2], bf[p][3], addr);
            }
#pragma unroll
            for (int mt = 0; mt < 2; mt++)
#pragma unroll
                for (int nt = 0; nt < 8; nt++)
                    mma_bf16(acc[mt][nt], af[mt], &bf[nt >> 1][(nt & 1) * 2]);
        }
    };

    // prologue
    load_A(0);
    issue_B(0, 0);
    store_A_both();
    CP_WAIT0();
    __syncthreads();

    for (int it = 0; it < 12; it++) {
        int buf = it & 1;
        int p = it - (it / 3) * 3;
        if (it < 11) issue_B(it + 1, buf ^ 1);
        if (p == 2 && it < 11) load_A(it / 3 + 1);
        compute(p == 2 ? sAlo : sAhi, sB[buf]);
        if (p == 2 && it < 11) {
            __syncthreads();   // all warps done reading sAhi/sAlo for this kc
            store_A_both();
        }
        CP_WAIT0();
        __syncthreads();
    }

    // epilogue: bias + relu
#pragma unroll
    for (int mt = 0; mt < 2; mt++) {
        int r0 = m0 + wm + mt * 16 + (lane >> 2);
        int r1 = r0 + 8;
#pragma unroll
        for (int nt = 0; nt < 8; nt++) {
            int n = wn + nt * 8 + (lane & 3) * 2;
            float b0 = __ldg(bias + n), b1 = __ldg(bias + n + 1);
            if (r0 < M) {
                float2 o;
                o.x = fmaxf(acc[mt][nt][0] + b0, 0.f);
                o.y = fmaxf(acc[mt][nt][1] + b1, 0.f);
                *(float2*)(C + (size_t)r0 * NF + n) = o;
            }
            if (r1 < M) {
                float2 o;
                o.x = fmaxf(acc[mt][nt][2] + b0, 0.f);
                o.y = fmaxf(acc[mt][nt][3] + b1, 0.f);
                *(float2*)(C + (size_t)r1 * NF + n) = o;
            }
        }
    }
}

// ---------------- CSR build ----------------
__global__ void hist_kernel(const int* __restrict__ erow, int E) {
    int i = blockIdx.x * blockDim.x + threadIdx.x;
    if (i < E) atomicAdd(&g_rowptr[erow[i]], 1);
}

__global__ void scan_kernel(int n) {
    __shared__ int part[1024];
    int t = threadIdx.x;
    int CH = (n + 1023) / 1024;
    int beg = t * CH;
    int end = min(beg + CH, n);
    int s = 0;
    for (int i = beg; i < end; i++) s += g_rowptr[i];
    part[t] = s;
    __syncthreads();
    for (int off = 1; off < 1024; off <<= 1) {
        int v = (t >= off) ? part[t - off] : 0;
        __syncthreads();
        part[t] += v;
        __syncthreads();
    }
    int base = (t == 0) ? 0 : part[t - 1];
    int run = base;
    for (int i = beg; i < end; i++) {
        int c = g_rowptr[i];
        g_rowptr[i] = run;
        g_cursor[i] = run;
        run += c;
    }
    if (t == 1023) g_rowptr[n] = part[1023];
}

__global__ void scatter_kernel(const int* __restrict__ erow,
                               const int* __restrict__ ecol,
                               const float* __restrict__ ew, int E) {
    int i = blockIdx.x * blockDim.x + threadIdx.x;
    if (i < E) {
        int r = erow[i];
        int pos = atomicAdd(&g_cursor[r], 1);
        g_cols[pos] = ecol[i];
        g_wts[pos] = ew[i];
    }
}

// ---------------- SPMM + residual: 2 warps per row (feature halves), unroll x4 ----------------
__global__ void spmm_res_kernel(const float* __restrict__ src,
                                float* __restrict__ dst, int n) {
    int gw = (blockIdx.x * blockDim.x + threadIdx.x) >> 5;
    int row = gw >> 1;
    if (row >= n) return;
    int half = gw & 1;
    int lane = threadIdx.x & 31;
    int fo = half * 32 + lane;  // float4 offset within row (0..63)
    const float4* s4 = (const float4*)src;
    float4 a = s4[(size_t)row * 64 + fo];  // residual
    int beg = g_rowptr[row], end = g_rowptr[row + 1];
    int e = beg;
    for (; e + 4 <= end; e += 4) {
        int c0 = __ldg(&g_cols[e]),     c1 = __ldg(&g_cols[e + 1]);
        int c2 = __ldg(&g_cols[e + 2]), c3 = __ldg(&g_cols[e + 3]);
        float w0 = __ldg(&g_wts[e]),     w1 = __ldg(&g_wts[e + 1]);
        float w2 = __ldg(&g_wts[e + 2]), w3 = __ldg(&g_wts[e + 3]);
        float4 v0 = s4[(size_t)c0 * 64 + fo];
        float4 v1 = s4[(size_t)c1 * 64 + fo];
        float4 v2 = s4[(size_t)c2 * 64 + fo];
        float4 v3 = s4[(size_t)c3 * 64 + fo];
        a.x += w0 * v0.x + w1 * v1.x + w2 * v2.x + w3 * v3.x;
        a.y += w0 * v0.y + w1 * v1.y + w2 * v2.y + w3 * v3.y;
        a.z += w0 * v0.z + w1 * v1.z + w2 * v2.z + w3 * v3.z;
        a.w += w0 * v0.w + w1 * v1.w + w2 * v2.w + w3 * v3.w;
    }
    for (; e < end; e++) {
        int c = __ldg(&g_cols[e]);
        float w = __ldg(&g_wts[e]);
        float4 v = s4[(size_t)c * 64 + fo];
        a.x += w * v.x; a.y += w * v.y; a.z += w * v.z; a.w += w * v.w;
    }
    ((float4*)dst)[(size_t)row * 64 + fo] = a;
}

// ---------------- fused final GEMM (N=40) + log_softmax ----------------
__global__ void __launch_bounds__(256) gemm40_lsm_kernel(
    const float* __restrict__ A, const float* __restrict__ B,
    const float* __restrict__ bias, float* __restrict__ out, int M) {
    __shared__ float As[16][132];
    __shared__ float Bs[16][64];
    __shared__ float ls[128][44];
    int tid = threadIdx.x;
    int tn = tid % 16, tm = tid / 16;
    int m0 = blockIdx.x * 128;
    float acc[8][4];
#pragma unroll
    for (int i = 0; i < 8; i++)
#pragma unroll
        for (int j = 0; j < 4; j++) acc[i][j] = 0.f;

    for (int k0 = 0; k0 < NF; k0 += 16) {
        for (int i = tid; i < 128 * 16; i += 256) {
            int r = i >> 4, c = i & 15;
            int gm = m0 + r;
            As[c][r] = (gm < M) ? A[(size_t)gm * NF + k0 + c] : 0.f;
        }
        for (int i = tid; i < 16 * 64; i += 256) {
            int r = i >> 6, c = i & 63;
            Bs[r][c] = (c < 40) ? B[(size_t)(k0 + r) * 40 + c] : 0.f;
        }
        __syncthreads();
#pragma unroll
        for (int k = 0; k < 16; k++) {
            float av[8], bv[4];
#pragma unroll
            for (int i = 0; i < 8; i++) av[i] = As[k][tm * 8 + i];
#pragma unroll
            for (int j = 0; j < 4; j++) bv[j] = Bs[k][tn * 4 + j];
#pragma unroll
            for (int i = 0; i < 8; i++)
#pragma unroll
                for (int j = 0; j < 4; j++) acc[i][j] += av[i] * bv[j];
        }
        __syncthreads();
    }
    // stage logits (+bias) to smem
#pragma unroll
    for (int i = 0; i < 8; i++)
#pragma unroll
        for (int j = 0; j < 4; j++) {
            int c = tn * 4 + j;
            if (c < 40) ls[tm * 8 + i][c] = acc[i][j] + bias[c];
        }
    __syncthreads();
    // log_softmax: 8 warps x 16 rows
    int wid = tid >> 5, lane = tid & 31;
    for (int i = 0; i < 16; i++) {
        int r = wid * 16 + i;
        int gr = m0 + r;
        if (gr >= M) continue;
        float v0 = ls[r][lane];
        float v1 = (lane < 8) ? ls[r][32 + lane] : -INFINITY;
        float m = fmaxf(v0, v1);
#pragma unroll
        for (int off = 16; off; off >>= 1) m = fmaxf(m, __shfl_xor_sync(0xffffffffu, m, off));
        float s = __expf(v0 - m) + ((lane < 8) ? __expf(v1 - m) : 0.f);
#pragma unroll
        for (int off = 16; off; off >>= 1) s += __shfl_xor_sync(0xffffffffu, s, off);
        float lse = m + __logf(s);
        out[(size_t)gr * 40 + lane] = v0 - lse;
        if (lane < 8) out[(size_t)gr * 40 + 32 + lane] = v1 - lse;
    }
}

// ---------------- launch ----------------
extern "C" void kernel_launch(void* const* d_in, const int* in_sizes, int n_in,
                              void* d_out, int out_size) {
    const float* x    = (const float*)d_in[0];
    const int*   erow = (const int*)d_in[1];
    const int*   ecol = (const int*)d_in[2];
    const float* ew   = (const float*)d_in[3];
    const float* W1 = (const float*)d_in[4];
    const float* b1 = (const float*)d_in[5];
    const float* W2 = (const float*)d_in[6];
    const float* b2 = (const float*)d_in[7];
    const float* W3 = (const float*)d_in[8];
    const float* b3 = (const float*)d_in[9];
    const float* W4 = (const float*)d_in[10];
    const float* b4 = (const float*)d_in[11];
    float* out = (float*)d_out;

    int E = in_sizes[1];
    int n = in_sizes[0] / NF;

    float *bufA, *bufB;
    __nv_bfloat16* wp;
    int* rowptr;
    cudaGetSymbolAddress((void**)&bufA, g_bufA);
    cudaGetSymbolAddress((void**)&bufB, g_bufB);
    cudaGetSymbolAddress((void**)&rowptr, g_rowptr);
    cudaGetSymbolAddress((void**)&wp, g_Wp);

    cudaFuncSetAttribute(gemm_bf16x3_kernel, cudaFuncAttributeMaxDynamicSharedMemorySize,
                         GEMM_SMEM);

    // CSR build first (so the new spmm is the 4th kernel launch -> gets profiled)
    cudaMemsetAsync(rowptr, 0, (size_t)(n + 1) * sizeof(int));
    hist_kernel<<<(E + 255) / 256, 256>>>(erow, E);
    scan_kernel<<<1, 1024>>>(n);
    scatter_kernel<<<(E + 255) / 256, 256>>>(erow, ecol, ew, E);

    int spmm_blocks = (n * 64 + 255) / 256;  // 2 warps per row
    int gemm_grid = (n + 127) / 128;

    // h0 = x + spmm(x)                     -> bufA   [4th kernel]
    spmm_res_kernel<<<spmm_blocks, 256>>>(x, bufA, n);

    // weight prep (transpose + bf16 split, kc-major K-extended)
    prep_w_bf16<<<256, 256>>>(W1, wp + 0 * (size_t)NF * KX);
    prep_w_bf16<<<256, 256>>>(W2, wp + 1 * (size_t)NF * KX);
    prep_w_bf16<<<256, 256>>>(W3, wp + 2 * (size_t)NF * KX);

    // h1 = relu(h0 @ W1 + b1)              -> bufB
    gemm_bf16x3_kernel<<<gemm_grid, 512, GEMM_SMEM>>>(bufA, wp + 0 * (size_t)NF * KX, b1,
                                                      bufB, n);
    // h2 = relu(h1 @ W2 + b2)              -> bufA
    gemm_bf16x3_kernel<<<gemm_grid, 512, GEMM_SMEM>>>(bufB, wp + 1 * (size_t)NF * KX, b2,
                                                      bufA, n);
    // h3 = h2 + spmm(h2)                   -> bufB
    spmm_res_kernel<<<spmm_blocks, 256>>>(bufA, bufB, n);
    // h4 = relu(h3 @ W3 + b3)              -> bufA
    gemm_bf16x3_kernel<<<gemm_grid, 512, GEMM_SMEM>>>(bufB, wp + 2 * (size_t)NF * KX, b3,
                                                      bufA, n);
    // logits + log_softmax                 -> d_out
    gemm40_lsm_kernel<<<gemm_grid, 256>>>(bufA, W4, b4, out, n);
}